// round 12
// baseline (speedup 1.0000x reference)
#include <cuda_runtime.h>
#include <cuda_bf16.h>

// ---------------------------------------------------------------------------
// VoxelHashTableDynamic fused kernel (fp32, packed f32x2 FMA path)
//
// Per CTA: 64 points. All intermediates in smem, transposed layout [d][m]
// with row stride 66 floats (8B aligned for LDS.64 point-pairs, conflict-free).
// Integer inputs (times, hash buffer) may arrive as int32 or int64 from the
// harness; a cheap in-kernel probe of the odd 32-bit words decides per launch.
// ---------------------------------------------------------------------------

#define PTS_PER_CTA 64
#define D_DIM       120
#define STRIDE      66            // padded row stride (even -> 8B aligned pairs)
#define BUF_FLOATS  (D_DIM * STRIDE)   // 7920
#define HEADS       8
#define HEAD_DIM    15
#define MOD_T       201
#define HASH_MASK   1048575LL
#define SMEM_BYTES  (7 * BUF_FLOATS * 4 + (3 * PTS_PER_CTA + 2) * 4)

__device__ __forceinline__ unsigned long long splat2(float x) {
    unsigned long long d;
    asm("mov.b64 %0, {%1, %1};" : "=l"(d) : "f"(x));
    return d;
}

__device__ __forceinline__ unsigned long long fma2(unsigned long long a,
                                                   unsigned long long b,
                                                   unsigned long long c) {
    unsigned long long d;
    asm("fma.rn.f32x2 %0, %1, %2, %3;" : "=l"(d) : "l"(a), "l"(b), "l"(c));
    return d;
}

__device__ __forceinline__ float2 unpack2(unsigned long long v) {
    float2 r;
    asm("mov.b64 {%0, %1}, %2;" : "=f"(r.x), "=f"(r.y) : "l"(v));
    return r;
}

// C_w[m][j] = sum_k A[m][k] * W_w[k][j] + B_w[j], for w = 0..NW-1.
// The NW weight matrices are CONSECUTIVE (stride 14400 floats), as are biases
// (stride 120). A_T is smem transposed [k][m] (stride 66). Outputs are written
// transposed [j][m] (stride 66).
// Thread tiling: mg = t/30 (8 groups of 8 m, as 4 packed pairs),
//                jg = t%30 (30 groups of 4 j). Threads t>=240 must not call.
template <int NW>
__device__ __forceinline__ void proj_pass(const float* __restrict__ W,
                                          const float* __restrict__ Bi,
                                          const float* __restrict__ A_T,
                                          float* C0, float* C1, float* C2,
                                          int mg, int jg) {
    float* Cs[3] = {C0, C1, C2};
    const int j0 = jg * 4;
    const int m0 = mg * 8;

    unsigned long long acc[NW][4][4];
#pragma unroll
    for (int w = 0; w < NW; ++w)
#pragma unroll
        for (int mm2 = 0; mm2 < 4; ++mm2)
#pragma unroll
            for (int jj = 0; jj < 4; ++jj)
                acc[w][mm2][jj] = splat2(Bi[w * 120 + j0 + jj]);

#pragma unroll 2
    for (int k = 0; k < D_DIM; ++k) {
        unsigned long long a2[4];
        const float* arow = A_T + k * STRIDE + m0;
#pragma unroll
        for (int mm2 = 0; mm2 < 4; ++mm2)
            a2[mm2] = *reinterpret_cast<const unsigned long long*>(arow + 2 * mm2);

#pragma unroll
        for (int w = 0; w < NW; ++w) {
            const float4 wv =
                *reinterpret_cast<const float4*>(W + w * 14400 + k * 120 + j0);
            unsigned long long ws[4] = {splat2(wv.x), splat2(wv.y),
                                        splat2(wv.z), splat2(wv.w)};
#pragma unroll
            for (int mm2 = 0; mm2 < 4; ++mm2)
#pragma unroll
                for (int jj = 0; jj < 4; ++jj)
                    acc[w][mm2][jj] = fma2(a2[mm2], ws[jj], acc[w][mm2][jj]);
        }
    }

#pragma unroll
    for (int w = 0; w < NW; ++w)
#pragma unroll
        for (int jj = 0; jj < 4; ++jj)
#pragma unroll
            for (int mm2 = 0; mm2 < 4; ++mm2)
                *reinterpret_cast<unsigned long long*>(
                    Cs[w] + (j0 + jj) * STRIDE + m0 + 2 * mm2) = acc[w][mm2][jj];
}

// Final projection: out[m][j] = sum_k A[m][k]*W[k][j] + B[j], written straight
// to global memory with validity masking (invalid rows -> zeros).
__device__ __forceinline__ void proj_out_global(const float* __restrict__ W,
                                                const float* __restrict__ Bi,
                                                const float* __restrict__ A_T,
                                                float* __restrict__ out,
                                                int ctaBase, const int* val_s,
                                                int M, int mg, int jg) {
    const int j0 = jg * 4;
    const int m0 = mg * 8;

    unsigned long long acc[4][4];
#pragma unroll
    for (int mm2 = 0; mm2 < 4; ++mm2)
#pragma unroll
        for (int jj = 0; jj < 4; ++jj)
            acc[mm2][jj] = splat2(Bi[j0 + jj]);

#pragma unroll 2
    for (int k = 0; k < D_DIM; ++k) {
        unsigned long long a2[4];
        const float* arow = A_T + k * STRIDE + m0;
#pragma unroll
        for (int mm2 = 0; mm2 < 4; ++mm2)
            a2[mm2] = *reinterpret_cast<const unsigned long long*>(arow + 2 * mm2);
        const float4 wv = *reinterpret_cast<const float4*>(W + k * 120 + j0);
        unsigned long long ws[4] = {splat2(wv.x), splat2(wv.y), splat2(wv.z),
                                    splat2(wv.w)};
#pragma unroll
        for (int mm2 = 0; mm2 < 4; ++mm2)
#pragma unroll
            for (int jj = 0; jj < 4; ++jj)
                acc[mm2][jj] = fma2(a2[mm2], ws[jj], acc[mm2][jj]);
    }

    const float4 zero4 = make_float4(0.f, 0.f, 0.f, 0.f);
#pragma unroll
    for (int mm2 = 0; mm2 < 4; ++mm2) {
        float2 p0 = unpack2(acc[mm2][0]);
        float2 p1 = unpack2(acc[mm2][1]);
        float2 p2 = unpack2(acc[mm2][2]);
        float2 p3 = unpack2(acc[mm2][3]);
        int mE = m0 + 2 * mm2;
        int mO = mE + 1;
        int gE = ctaBase + mE;
        int gO = ctaBase + mO;
        if (gE < M) {
            float4 v = make_float4(p0.x, p1.x, p2.x, p3.x);
            *reinterpret_cast<float4*>(out + (size_t)gE * 120 + j0) =
                val_s[mE] ? v : zero4;
        }
        if (gO < M) {
            float4 v = make_float4(p0.y, p1.y, p2.y, p3.y);
            *reinterpret_cast<float4*>(out + (size_t)gO * 120 + j0) =
                val_s[mO] ? v : zero4;
        }
    }
}

// 2-token attention: o0 = softmax([q0.k0, q0.k1]/sqrt(hd)) @ [v0; v1],
// per head, written back in place of PQ. All (m,h) slices disjoint per task.
__device__ __forceinline__ void attention(float* PQ, const float* PK0,
                                          const float* PK1, const float* PV0,
                                          const float* PV1, int t) {
    const float SC = 0.25819888974716113f;  // 1/sqrt(15)
#pragma unroll
    for (int r = 0; r < 2; ++r) {
        int u = t + 256 * r;          // 512 tasks = 64 points * 8 heads
        int m = u & 63;
        int h = u >> 6;
        int base = h * HEAD_DIM;
        float s00 = 0.f, s01 = 0.f;
#pragma unroll
        for (int d = 0; d < HEAD_DIM; ++d) {
            int idx = (base + d) * STRIDE + m;
            float q = PQ[idx];
            s00 += q * PK0[idx];
            s01 += q * PK1[idx];
        }
        float p00 = 1.0f / (1.0f + expf((s01 - s00) * SC));
        float p01 = 1.0f - p00;
#pragma unroll
        for (int d = 0; d < HEAD_DIM; ++d) {
            int idx = (base + d) * STRIDE + m;
            PQ[idx] = p00 * PV0[idx] + p01 * PV1[idx];
        }
    }
}

__global__ __launch_bounds__(256, 1) void voxel_fused_kernel(
    const float* __restrict__ pts, const void* __restrict__ times_raw,
    const void* __restrict__ buf_raw, const float* __restrict__ statf,
    const float* __restrict__ dynf, const float* __restrict__ temb,
    const float* __restrict__ Wtd, const float* __restrict__ Btd,
    const float* __restrict__ Wsd, const float* __restrict__ Bsd,
    float* __restrict__ out, int M) {
    extern __shared__ float sm[];
    float* XA  = sm;
    float* XB  = sm + 1 * BUF_FLOATS;
    float* PQ  = sm + 2 * BUF_FLOATS;
    float* PK0 = sm + 3 * BUF_FLOATS;
    float* PK1 = sm + 4 * BUF_FLOATS;
    float* PV0 = sm + 5 * BUF_FLOATS;
    float* PV1 = sm + 6 * BUF_FLOATS;
    int* vi_s  = (int*)(sm + 7 * BUF_FLOATS);
    int* ti_s  = vi_s + PTS_PER_CTA;
    int* val_s = ti_s + PTS_PER_CTA;
    int* fl    = val_s + PTS_PER_CTA;   // fl[0]=buf is int32, fl[1]=times is int32

    const int t = threadIdx.x;
    const int ctaBase = blockIdx.x * PTS_PER_CTA;

    // ---- dtype probe: odd 32-bit words are sign/zero-extension iff int64 ----
    // Always in-bounds under either dtype (indices < element count).
    if (t < 2) fl[t] = 0;
    __syncthreads();
    if (t < 64) {
        const int* b32 = (const int*)buf_raw;
        int bad = 0;
#pragma unroll
        for (int r = 0; r < 2; ++r) {
            int w = b32[2 * (t + 64 * r) + 1];   // entries 1..255 odd / high words
            if (w != 0 && w != -1) bad = 1;
        }
        if (bad) atomicOr(&fl[0], 1);
        const int* q32 = (const int*)times_raw;
        int badt = 0;
#pragma unroll
        for (int r = 0; r < 4; ++r) {
            if (q32[2 * (t + 64 * r) + 1] != 0) badt = 1;
        }
        if (badt) atomicOr(&fl[1], 1);
    }
    __syncthreads();
    const bool buf32 = fl[0] != 0;
    const bool tim32 = fl[1] != 0;

    // ---- per-point metadata: hash lookup, validity, time index ----
    if (t < PTS_PER_CTA) {
        int g = ctaBase + t;
        int vi = 0, va = 0, ti = 0;
        if (g < M) {
            float px = pts[3 * g + 0];
            float py = pts[3 * g + 1];
            float pz = pts[3 * g + 2];
            // must match reference bit-for-bit: f32 IEEE divide, then floor
            long long g0 = (long long)floorf(__fdiv_rn(px, 0.1f));
            long long g1 = (long long)floorf(__fdiv_rn(py, 0.1f));
            long long g2 = (long long)floorf(__fdiv_rn(pz, 0.1f));
            long long h =
                (g0 * 73856093LL + g1 * 19349669LL + g2 * 83492791LL) & HASH_MASK;
            long long v = buf32 ? (long long)((const int*)buf_raw)[h]
                                : ((const long long*)buf_raw)[h];
            va = (v >= 0) ? 1 : 0;
            vi = va ? (int)v : 0;
            long long tv = tim32 ? (long long)((const int*)times_raw)[g]
                                 : ((const long long*)times_raw)[g];
            ti = (int)(tv % MOD_T);
            if (ti < 0) ti += MOD_T;
        }
        vi_s[t] = vi;
        ti_s[t] = ti;
        val_s[t] = va;
    }
    __syncthreads();

    // ---- gather dynamic features + time embeddings (transposed) ----
    for (int e = t; e < PTS_PER_CTA * D_DIM; e += 256) {
        int m = e / D_DIM;
        int d = e - m * D_DIM;
        XA[d * STRIDE + m] = dynf[(size_t)vi_s[m] * D_DIM + d];
        XB[d * STRIDE + m] = temb[(size_t)ti_s[m] * D_DIM + d];
    }
    __syncthreads();

    const int mg = t / 30;
    const int jg = t - mg * 30;
    const bool act = (t < 240);

    // ================= Fusion 1: cond = fusion(df, te, td) =================
    if (act) {
        // q0 = df@W0, k0 = df@W1, v0 = df@W2  (W0..W2 consecutive)
        proj_pass<3>(Wtd, Btd, XA, PQ, PK0, PV0, mg, jg);
        // k1 = te@W1, v1 = te@W2
        proj_pass<2>(Wtd + 14400, Btd + 120, XB, PK1, PV1, nullptr, mg, jg);
    }
    __syncthreads();
    attention(PQ, PK0, PK1, PV0, PV1, t);
    __syncthreads();
    if (act) {
        // cond = o0@W3 + B3 -> XB (te no longer needed)
        proj_pass<1>(Wtd + 43200, Btd + 360, PQ, XB, nullptr, nullptr, mg, jg);
    }
    __syncthreads();

    // ---- gather static features into XA ----
    for (int e = t; e < PTS_PER_CTA * D_DIM; e += 256) {
        int m = e / D_DIM;
        int d = e - m * D_DIM;
        XA[d * STRIDE + m] = statf[(size_t)vi_s[m] * D_DIM + d];
    }
    __syncthreads();

    // ================ Fusion 2: fused = fusion(sf, cond, sd) ===============
    if (act) {
        proj_pass<3>(Wsd, Bsd, XA, PQ, PK0, PV0, mg, jg);
        proj_pass<2>(Wsd + 14400, Bsd + 120, XB, PK1, PV1, nullptr, mg, jg);
    }
    __syncthreads();
    attention(PQ, PK0, PK1, PV0, PV1, t);
    __syncthreads();
    if (act) {
        proj_out_global(Wsd + 43200, Bsd + 360, PQ, out, ctaBase, val_s, M, mg, jg);
    }
}

extern "C" void kernel_launch(void* const* d_in, const int* in_sizes, int n_in,
                              void* d_out, int out_size) {
    // Positional defaults (reference dict order) ...
    const void* P[10];
    for (int i = 0; i < 10 && i < n_in; ++i) P[i] = d_in[i];
    int M = (n_in > 1) ? in_sizes[1] : 200000;

    // ... then override by size signature (robust to reordered metadata).
    // Unique sizes: pts=600000, times=200000, buf=1048576, temb=24120.
    // Tied sizes keep first-seen order: W (57600 x2), B (480 x2), feats (big x2).
    {
        int nW = 0, nB = 0, nF = 0;
        for (int i = 0; i < n_in && i < 16; ++i) {
            int s = in_sizes[i];
            if (s == 600000)       P[0] = d_in[i];
            else if (s == 200000)  { P[1] = d_in[i]; M = s; }
            else if (s == 1048576) P[2] = d_in[i];
            else if (s == 24120)   P[5] = d_in[i];
            else if (s == 57600)   { P[nW == 0 ? 6 : 8] = d_in[i]; nW++; }
            else if (s == 480)     { P[nB == 0 ? 7 : 9] = d_in[i]; nB++; }
            else if (s > 1048576 && s % 120 == 0) { P[nF == 0 ? 3 : 4] = d_in[i]; nF++; }
        }
    }

    const float* pts   = (const float*)P[0];
    const void*  times = P[1];
    const void*  buf   = P[2];
    const float* statf = (const float*)P[3];
    const float* dynf  = (const float*)P[4];
    const float* temb  = (const float*)P[5];
    const float* Wtd   = (const float*)P[6];
    const float* Btd   = (const float*)P[7];
    const float* Wsd   = (const float*)P[8];
    const float* Bsd   = (const float*)P[9];
    float* out = (float*)d_out;

    cudaFuncSetAttribute(voxel_fused_kernel,
                         cudaFuncAttributeMaxDynamicSharedMemorySize, SMEM_BYTES);

    int grid = (M + PTS_PER_CTA - 1) / PTS_PER_CTA;
    voxel_fused_kernel<<<grid, 256, SMEM_BYTES>>>(
        pts, times, buf, statf, dynf, temb, Wtd, Btd, Wsd, Bsd, out, M);
}

// round 13
// speedup vs baseline: 1.5104x; 1.5104x over previous
#include <cuda_runtime.h>
#include <cuda_bf16.h>

// ---------------------------------------------------------------------------
// VoxelHashTableDynamic fused kernel (fp32, packed f32x2 FMA path)
//
// Per CTA: 32 points (half tile -> 2 CTAs/SM for latency hiding).
// All intermediates in smem, transposed layout [d][m] with row stride 34
// floats (8B aligned pairs, conflict-free). Integer inputs (times, hash
// buffer) may arrive as int32 or int64; an in-kernel probe decides.
// ---------------------------------------------------------------------------

#define PTS_PER_CTA 32
#define D_DIM       120
#define STRIDE      34            // padded row stride (even -> 8B aligned pairs)
#define BUF_FLOATS  (D_DIM * STRIDE)   // 4080
#define HEADS       8
#define HEAD_DIM    15
#define MOD_T       201
#define HASH_MASK   1048575LL
#define SMEM_BYTES  (7 * BUF_FLOATS * 4 + (3 * PTS_PER_CTA + 2) * 4)

__device__ __forceinline__ unsigned long long splat2(float x) {
    unsigned long long d;
    asm("mov.b64 %0, {%1, %1};" : "=l"(d) : "f"(x));
    return d;
}

__device__ __forceinline__ unsigned long long fma2(unsigned long long a,
                                                   unsigned long long b,
                                                   unsigned long long c) {
    unsigned long long d;
    asm("fma.rn.f32x2 %0, %1, %2, %3;" : "=l"(d) : "l"(a), "l"(b), "l"(c));
    return d;
}

__device__ __forceinline__ float2 unpack2(unsigned long long v) {
    float2 r;
    asm("mov.b64 {%0, %1}, %2;" : "=f"(r.x), "=f"(r.y) : "l"(v));
    return r;
}

// C_w[m][j] = sum_k A[m][k] * W_w[k][j] + B_w[j], for w = 0..NW-1.
// The NW weight matrices are CONSECUTIVE (stride 14400 floats), as are biases
// (stride 120). A_T is smem transposed [k][m] (stride 34). Outputs are written
// transposed [j][m] (stride 34).
// Thread tiling: mg = t/30 (8 groups of 4 m, as 2 packed pairs),
//                jg = t%30 (30 groups of 4 j). Threads t>=240 must not call.
template <int NW>
__device__ __forceinline__ void proj_pass(const float* __restrict__ W,
                                          const float* __restrict__ Bi,
                                          const float* __restrict__ A_T,
                                          float* C0, float* C1, float* C2,
                                          int mg, int jg) {
    float* Cs[3] = {C0, C1, C2};
    const int j0 = jg * 4;
    const int m0 = mg * 4;

    unsigned long long acc[NW][2][4];
#pragma unroll
    for (int w = 0; w < NW; ++w)
#pragma unroll
        for (int p = 0; p < 2; ++p)
#pragma unroll
            for (int jj = 0; jj < 4; ++jj)
                acc[w][p][jj] = splat2(Bi[w * 120 + j0 + jj]);

#pragma unroll 4
    for (int k = 0; k < D_DIM; ++k) {
        unsigned long long a2[2];
        const float* arow = A_T + k * STRIDE + m0;
#pragma unroll
        for (int p = 0; p < 2; ++p)
            a2[p] = *reinterpret_cast<const unsigned long long*>(arow + 2 * p);

#pragma unroll
        for (int w = 0; w < NW; ++w) {
            const float4 wv =
                *reinterpret_cast<const float4*>(W + w * 14400 + k * 120 + j0);
            unsigned long long ws[4] = {splat2(wv.x), splat2(wv.y),
                                        splat2(wv.z), splat2(wv.w)};
#pragma unroll
            for (int p = 0; p < 2; ++p)
#pragma unroll
                for (int jj = 0; jj < 4; ++jj)
                    acc[w][p][jj] = fma2(a2[p], ws[jj], acc[w][p][jj]);
        }
    }

#pragma unroll
    for (int w = 0; w < NW; ++w)
#pragma unroll
        for (int jj = 0; jj < 4; ++jj)
#pragma unroll
            for (int p = 0; p < 2; ++p)
                *reinterpret_cast<unsigned long long*>(
                    Cs[w] + (j0 + jj) * STRIDE + m0 + 2 * p) = acc[w][p][jj];
}

// Final projection: out[m][j] = sum_k A[m][k]*W[k][j] + B[j], written straight
// to global memory with validity masking (invalid rows -> zeros).
__device__ __forceinline__ void proj_out_global(const float* __restrict__ W,
                                                const float* __restrict__ Bi,
                                                const float* __restrict__ A_T,
                                                float* __restrict__ out,
                                                int ctaBase, const int* val_s,
                                                int M, int mg, int jg) {
    const int j0 = jg * 4;
    const int m0 = mg * 4;

    unsigned long long acc[2][4];
#pragma unroll
    for (int p = 0; p < 2; ++p)
#pragma unroll
        for (int jj = 0; jj < 4; ++jj)
            acc[p][jj] = splat2(Bi[j0 + jj]);

#pragma unroll 4
    for (int k = 0; k < D_DIM; ++k) {
        unsigned long long a2[2];
        const float* arow = A_T + k * STRIDE + m0;
#pragma unroll
        for (int p = 0; p < 2; ++p)
            a2[p] = *reinterpret_cast<const unsigned long long*>(arow + 2 * p);
        const float4 wv = *reinterpret_cast<const float4*>(W + k * 120 + j0);
        unsigned long long ws[4] = {splat2(wv.x), splat2(wv.y), splat2(wv.z),
                                    splat2(wv.w)};
#pragma unroll
        for (int p = 0; p < 2; ++p)
#pragma unroll
            for (int jj = 0; jj < 4; ++jj)
                acc[p][jj] = fma2(a2[p], ws[jj], acc[p][jj]);
    }

    const float4 zero4 = make_float4(0.f, 0.f, 0.f, 0.f);
#pragma unroll
    for (int p = 0; p < 2; ++p) {
        float2 p0 = unpack2(acc[p][0]);
        float2 p1 = unpack2(acc[p][1]);
        float2 p2 = unpack2(acc[p][2]);
        float2 p3 = unpack2(acc[p][3]);
        int mE = m0 + 2 * p;
        int mO = mE + 1;
        int gE = ctaBase + mE;
        int gO = ctaBase + mO;
        if (gE < M) {
            float4 v = make_float4(p0.x, p1.x, p2.x, p3.x);
            *reinterpret_cast<float4*>(out + (size_t)gE * 120 + j0) =
                val_s[mE] ? v : zero4;
        }
        if (gO < M) {
            float4 v = make_float4(p0.y, p1.y, p2.y, p3.y);
            *reinterpret_cast<float4*>(out + (size_t)gO * 120 + j0) =
                val_s[mO] ? v : zero4;
        }
    }
}

// 2-token attention: o0 = softmax([q0.k0, q0.k1]/sqrt(hd)) @ [v0; v1],
// per head, written back in place of PQ. 256 tasks = 32 points * 8 heads.
__device__ __forceinline__ void attention(float* PQ, const float* PK0,
                                          const float* PK1, const float* PV0,
                                          const float* PV1, int t) {
    const float SC = 0.25819888974716113f;  // 1/sqrt(15)
    int m = t & 31;
    int h = t >> 5;
    int base = h * HEAD_DIM;
    float s00 = 0.f, s01 = 0.f;
#pragma unroll
    for (int d = 0; d < HEAD_DIM; ++d) {
        int idx = (base + d) * STRIDE + m;
        float q = PQ[idx];
        s00 += q * PK0[idx];
        s01 += q * PK1[idx];
    }
    float p00 = 1.0f / (1.0f + __expf((s01 - s00) * SC));
    float p01 = 1.0f - p00;
#pragma unroll
    for (int d = 0; d < HEAD_DIM; ++d) {
        int idx = (base + d) * STRIDE + m;
        PQ[idx] = p00 * PV0[idx] + p01 * PV1[idx];
    }
}

__global__ __launch_bounds__(256, 2) void voxel_fused_kernel(
    const float* __restrict__ pts, const void* __restrict__ times_raw,
    const void* __restrict__ buf_raw, const float* __restrict__ statf,
    const float* __restrict__ dynf, const float* __restrict__ temb,
    const float* __restrict__ Wtd, const float* __restrict__ Btd,
    const float* __restrict__ Wsd, const float* __restrict__ Bsd,
    float* __restrict__ out, int M) {
    extern __shared__ float sm[];
    float* XA  = sm;
    float* XB  = sm + 1 * BUF_FLOATS;
    float* PQ  = sm + 2 * BUF_FLOATS;
    float* PK0 = sm + 3 * BUF_FLOATS;
    float* PK1 = sm + 4 * BUF_FLOATS;
    float* PV0 = sm + 5 * BUF_FLOATS;
    float* PV1 = sm + 6 * BUF_FLOATS;
    int* vi_s  = (int*)(sm + 7 * BUF_FLOATS);
    int* ti_s  = vi_s + PTS_PER_CTA;
    int* val_s = ti_s + PTS_PER_CTA;
    int* fl    = val_s + PTS_PER_CTA;   // fl[0]=buf is int32, fl[1]=times is int32

    const int t = threadIdx.x;
    const int ctaBase = blockIdx.x * PTS_PER_CTA;

    // ---- dtype probe: odd 32-bit words are sign/zero-extension iff int64 ----
    // Always in-bounds under either dtype (indices < element count).
    if (t < 2) fl[t] = 0;
    __syncthreads();
    if (t < 64) {
        const int* b32 = (const int*)buf_raw;
        int bad = 0;
#pragma unroll
        for (int r = 0; r < 2; ++r) {
            int w = b32[2 * (t + 64 * r) + 1];   // entries 1..255 odd / high words
            if (w != 0 && w != -1) bad = 1;
        }
        if (bad) atomicOr(&fl[0], 1);
        const int* q32 = (const int*)times_raw;
        int badt = 0;
#pragma unroll
        for (int r = 0; r < 4; ++r) {
            if (q32[2 * (t + 64 * r) + 1] != 0) badt = 1;
        }
        if (badt) atomicOr(&fl[1], 1);
    }
    __syncthreads();
    const bool buf32 = fl[0] != 0;
    const bool tim32 = fl[1] != 0;

    // ---- per-point metadata: hash lookup, validity, time index ----
    if (t < PTS_PER_CTA) {
        int g = ctaBase + t;
        int vi = 0, va = 0, ti = 0;
        if (g < M) {
            float px = pts[3 * g + 0];
            float py = pts[3 * g + 1];
            float pz = pts[3 * g + 2];
            // must match reference bit-for-bit: f32 IEEE divide, then floor
            long long g0 = (long long)floorf(__fdiv_rn(px, 0.1f));
            long long g1 = (long long)floorf(__fdiv_rn(py, 0.1f));
            long long g2 = (long long)floorf(__fdiv_rn(pz, 0.1f));
            long long h =
                (g0 * 73856093LL + g1 * 19349669LL + g2 * 83492791LL) & HASH_MASK;
            long long v = buf32 ? (long long)((const int*)buf_raw)[h]
                                : ((const long long*)buf_raw)[h];
            va = (v >= 0) ? 1 : 0;
            vi = va ? (int)v : 0;
            long long tv = tim32 ? (long long)((const int*)times_raw)[g]
                                 : ((const long long*)times_raw)[g];
            ti = (int)(tv % MOD_T);
            if (ti < 0) ti += MOD_T;
        }
        vi_s[t] = vi;
        ti_s[t] = ti;
        val_s[t] = va;
    }
    __syncthreads();

    // ---- gather dynamic features + time embeddings (transposed) ----
    for (int e = t; e < PTS_PER_CTA * D_DIM; e += 256) {
        int m = e / D_DIM;
        int d = e - m * D_DIM;
        XA[d * STRIDE + m] = dynf[(size_t)vi_s[m] * D_DIM + d];
        XB[d * STRIDE + m] = temb[(size_t)ti_s[m] * D_DIM + d];
    }
    __syncthreads();

    const int mg = t / 30;
    const int jg = t - mg * 30;
    const bool act = (t < 240);

    // ================= Fusion 1: cond = fusion(df, te, td) =================
    if (act) {
        // q0 = df@W0, k0 = df@W1, v0 = df@W2  (W0..W2 consecutive)
        proj_pass<3>(Wtd, Btd, XA, PQ, PK0, PV0, mg, jg);
        // k1 = te@W1, v1 = te@W2
        proj_pass<2>(Wtd + 14400, Btd + 120, XB, PK1, PV1, nullptr, mg, jg);
    }
    __syncthreads();
    attention(PQ, PK0, PK1, PV0, PV1, t);
    __syncthreads();
    if (act) {
        // cond = o0@W3 + B3 -> XB (te no longer needed)
        proj_pass<1>(Wtd + 43200, Btd + 360, PQ, XB, nullptr, nullptr, mg, jg);
    }
    __syncthreads();

    // ---- gather static features into XA ----
    for (int e = t; e < PTS_PER_CTA * D_DIM; e += 256) {
        int m = e / D_DIM;
        int d = e - m * D_DIM;
        XA[d * STRIDE + m] = statf[(size_t)vi_s[m] * D_DIM + d];
    }
    __syncthreads();

    // ================ Fusion 2: fused = fusion(sf, cond, sd) ===============
    if (act) {
        proj_pass<3>(Wsd, Bsd, XA, PQ, PK0, PV0, mg, jg);
        proj_pass<2>(Wsd + 14400, Bsd + 120, XB, PK1, PV1, nullptr, mg, jg);
    }
    __syncthreads();
    attention(PQ, PK0, PK1, PV0, PV1, t);
    __syncthreads();
    if (act) {
        proj_out_global(Wsd + 43200, Bsd + 360, PQ, out, ctaBase, val_s, M, mg, jg);
    }
}

extern "C" void kernel_launch(void* const* d_in, const int* in_sizes, int n_in,
                              void* d_out, int out_size) {
    // Positional defaults (reference dict order) ...
    const void* P[10];
    for (int i = 0; i < 10 && i < n_in; ++i) P[i] = d_in[i];
    int M = (n_in > 1) ? in_sizes[1] : 200000;

    // ... then override by size signature (robust to reordered metadata).
    // Unique sizes: pts=600000, times=200000, buf=1048576, temb=24120.
    // Tied sizes keep first-seen order: W (57600 x2), B (480 x2), feats (big x2).
    {
        int nW = 0, nB = 0, nF = 0;
        for (int i = 0; i < n_in && i < 16; ++i) {
            int s = in_sizes[i];
            if (s == 600000)       P[0] = d_in[i];
            else if (s == 200000)  { P[1] = d_in[i]; M = s; }
            else if (s == 1048576) P[2] = d_in[i];
            else if (s == 24120)   P[5] = d_in[i];
            else if (s == 57600)   { P[nW == 0 ? 6 : 8] = d_in[i]; nW++; }
            else if (s == 480)     { P[nB == 0 ? 7 : 9] = d_in[i]; nB++; }
            else if (s > 1048576 && s % 120 == 0) { P[nF == 0 ? 3 : 4] = d_in[i]; nF++; }
        }
    }

    const float* pts   = (const float*)P[0];
    const void*  times = P[1];
    const void*  buf   = P[2];
    const float* statf = (const float*)P[3];
    const float* dynf  = (const float*)P[4];
    const float* temb  = (const float*)P[5];
    const float* Wtd   = (const float*)P[6];
    const float* Btd   = (const float*)P[7];
    const float* Wsd   = (const float*)P[8];
    const float* Bsd   = (const float*)P[9];
    float* out = (float*)d_out;

    cudaFuncSetAttribute(voxel_fused_kernel,
                         cudaFuncAttributeMaxDynamicSharedMemorySize, SMEM_BYTES);

    int grid = (M + PTS_PER_CTA - 1) / PTS_PER_CTA;
    voxel_fused_kernel<<<grid, 256, SMEM_BYTES>>>(
        pts, times, buf, statf, dynf, temb, Wtd, Btd, Wsd, Bsd, out, M);
}